// round 3
// baseline (speedup 1.0000x reference)
#include <cuda_runtime.h>
#include <math.h>
#include <stdint.h>
#include <string.h>

#define PI_F 3.14159265358979323846f
#define RCUTF 5.0f
#define NT 10
#define WARPS 8

// ============================================================================
// Host-side exact replication of numpy RandomState(seed).standard_normal(...)
// (MT19937 + legacy polar/Marsaglia gauss with cached second value)
// ============================================================================
struct MT19937 {
    uint32_t mt[624];
    int mti;
    void seed(uint32_t s) {
        mt[0] = s;
        for (int i = 1; i < 624; i++)
            mt[i] = 1812433253u * (mt[i-1] ^ (mt[i-1] >> 30)) + (uint32_t)i;
        mti = 624;
    }
    uint32_t next() {
        if (mti >= 624) {
            for (int i = 0; i < 624; i++) {
                uint32_t y = (mt[i] & 0x80000000u) | (mt[(i+1) % 624] & 0x7fffffffu);
                mt[i] = mt[(i+397) % 624] ^ (y >> 1) ^ ((y & 1u) ? 2567483615u : 0u);
            }
            mti = 0;
        }
        uint32_t y = mt[mti++];
        y ^= y >> 11;
        y ^= (y << 7)  & 2636928640u;
        y ^= (y << 15) & 4022730752u;
        y ^= y >> 18;
        return y;
    }
    double rdouble() {
        uint32_t a = next() >> 5, b = next() >> 6;
        return (a * 67108864.0 + b) / 9007199254740992.0;
    }
};
struct GaussGen {
    MT19937 mt;
    bool has;
    double cached;
    void init(uint32_t s) { mt.seed(s); has = false; cached = 0.0; }
    double next() {
        if (has) { has = false; return cached; }
        double x1, x2, r2;
        do {
            x1 = 2.0 * mt.rdouble() - 1.0;
            x2 = 2.0 * mt.rdouble() - 1.0;
            r2 = x1 * x1 + x2 * x2;
        } while (r2 >= 1.0 || r2 == 0.0);
        double f = sqrt(-2.0 * log(r2) / r2);
        cached = f * x1; has = true;
        return f * x2;
    }
};

struct CGParam { float v[966]; };

static void fill_cg(float* out) {
    int off = 0;
    for (int l1 = 0; l1 < 3; l1++)
        for (int l2 = 0; l2 <= l1; l2++)
            for (int l3 = l1 - l2; l3 <= l1 + l2; l3++) {
                GaussGen g; g.init((uint32_t)(1000 + l1*100 + l2*10 + l3));
                int cnt = (2*l1+1) * (2*l2+1) * (2*l3+1);
                for (int q = 0; q < cnt; q++)
                    out[off++] = (float)g.next();
            }
    // off == 966
}

// ============================================================================
// Compile-time index tables
// ============================================================================
struct Tables {
    unsigned char tri_x[21], tri_y[21];      // tri index -> (x,y), x<=y
    unsigned char et_xy[124], et_ag[124];    // E tasks (xy, a'_global)
    short cgoff[3][3][5];                    // cg flat offsets per (l1,l2,l3)
    unsigned char om_xy[196], om_l1[196], om_l2[196], om_mn[196]; // output map
    int n_et;
};

constexpr int trif(int x, int y) {
    int lo = x < y ? x : y, hi = x < y ? y : x;
    return hi * (hi + 1) / 2 + lo;
}

constexpr Tables makeTables() {
    Tables t{};
    for (int x = 0; x < 6; x++)
        for (int y = x; y < 6; y++) {
            t.tri_x[trif(x,y)] = (unsigned char)x;
            t.tri_y[trif(x,y)] = (unsigned char)y;
        }
    const int base[3] = {0, 3, 5};
    const int adim[3] = {3, 2, 1};
    {
        int off = 0;
        for (int l1 = 0; l1 < 3; l1++)
            for (int l2 = 0; l2 <= l1; l2++)
                for (int l3 = l1 - l2; l3 <= l1 + l2; l3++) {
                    t.cgoff[l1][l2][l3] = (short)off;
                    off += (2*l1+1) * (2*l2+1) * (2*l3+1);
                }
    }
    {
        bool seen[21][25] = {};
        int n = 0;
        for (int l1 = 0; l1 < 3; l1++)
            for (int l2 = 0; l2 <= l1; l2++)
                for (int xa = 0; xa < adim[l1]; xa++)
                    for (int xb = 0; xb < adim[l2]; xb++) {
                        int xy = trif(base[l1] + xa, base[l2] + xb);
                        for (int l3 = l1 - l2; l3 <= l1 + l2; l3++)
                            for (int ap = 0; ap < 2*l3 + 1; ap++) {
                                int ag = l3*l3 + ap;
                                if (!seen[xy][ag]) {
                                    seen[xy][ag] = true;
                                    t.et_xy[n] = (unsigned char)xy;
                                    t.et_ag[n] = (unsigned char)ag;
                                    n++;
                                }
                            }
                    }
        t.n_et = n; // 121
    }
    for (int r = 0; r < 14; r++)
        for (int c = 0; c < 14; c++) {
            int lr = r < 3 ? 0 : (r < 9 ? 1 : 2);
            int xr = r - (lr == 0 ? 0 : (lr == 1 ? 3 : 9));
            int lc = c < 3 ? 0 : (c < 9 ? 1 : 2);
            int xc = c - (lc == 0 ? 0 : (lc == 1 ? 3 : 9));
            int l1 = 0, l2 = 0, X = 0, Y = 0;
            if (lr >= lc) { l1 = lr; l2 = lc; X = xr; Y = xc; }
            else          { l1 = lc; l2 = lr; X = xc; Y = xr; }
            int N = 2*l2 + 1, A = adim[l1], B = adim[l2];
            int flat = X * (N * B) + Y;
            int b = flat % B; int tmp = flat / B;
            int a = tmp % A; tmp /= A;
            int n2 = tmp % N; int m = tmp / N;
            int idx = r * 14 + c;
            t.om_xy[idx] = (unsigned char)trif(base[l1] + a, base[l2] + b);
            t.om_l1[idx] = (unsigned char)l1;
            t.om_l2[idx] = (unsigned char)l2;
            t.om_mn[idx] = (unsigned char)(m * N + n2);
        }
    return t;
}

__constant__ Tables TBc = makeTables();

// ============================================================================
// Main kernel: one warp per pair, 8 pairs per 256-thread CTA
// ============================================================================
#define WSLOT 1088  // floats per warp in dynamic smem

__global__ void __launch_bounds__(256) op_kernel(
    const float* __restrict__ c0, const float* __restrict__ c1,
    const float* __restrict__ c2, const float* __restrict__ c3,
    const float* __restrict__ c4,
    const float* __restrict__ Rpos, const float* __restrict__ w_rad,
    const float* __restrict__ weight,
    const float* __restrict__ s_col, const float* __restrict__ p_col,
    const float* __restrict__ d_col,
    const int* __restrict__ Z, const int* __restrict__ pairs,
    const int* __restrict__ aidx,
    float* __restrict__ out, int Pn,
    const __grid_constant__ CGParam cgp)
{
    __shared__ float wrad_s[2560];   // [l][k][f]
    __shared__ float cg_s[966];
    __shared__ float coll_s[96];     // 6 rows x 16
    __shared__ float collp_s[21 * 17];
    __shared__ Tables TBs;
    extern __shared__ float dyn[];

    int tid = threadIdx.x, w = tid >> 5, lane = tid & 31;

    for (int idx = tid; idx < 2560; idx += 256) wrad_s[idx] = w_rad[idx];
    for (int idx = tid; idx < 966;  idx += 256) cg_s[idx] = cgp.v[idx];
    if (tid < 96) {
        float v;
        if (tid < 48)      v = s_col[tid];
        else if (tid < 80) v = p_col[tid - 48];
        else               v = d_col[tid - 80];
        coll_s[tid] = v;
    }
    {
        const char* src = (const char*)&TBc;
        char* dst = (char*)&TBs;
        for (int idx = tid; idx < (int)sizeof(Tables); idx += 256) dst[idx] = src[idx];
    }
    __syncthreads();
    for (int idx = tid; idx < 336; idx += 256) {
        int t = idx >> 4, f = idx & 15;
        collp_s[t * 17 + f] = coll_s[TBs.tri_x[t] * 16 + f] * coll_s[TBs.tri_y[t] * 16 + f];
    }
    __syncthreads();

    int p = blockIdx.x * WARPS + w;
    if (p >= Pn) return;

    float* Wp   = dyn + w * WSLOT;
    float* rbf  = Wp;            // 32
    float* gsh  = Wp + 32;       // 80  [l][f]
    float* coutS = Wp + 112;     // 25*17=425  [a_global][f]
    float* scr  = Wp + 544;      // 544 scratch: phase B = cin(144)+gw(272); phase C/D = E(525)
    float* cin  = scr;           // [m][c] 9*16
    float* gws  = scr + 144;     // [b][c] 16*17
    float* Ew   = scr;           // [xy][ag] 21*25

    int i = pairs[2 * p], j = pairs[2 * p + 1];
    int ai = aidx[p];
    int t1 = Z[pairs[2 * ai]], t2 = Z[pairs[2 * ai + 1]];

    float dx = Rpos[3*i+0] - Rpos[3*j+0];
    float dy = Rpos[3*i+1] - Rpos[3*j+1];
    float dz = Rpos[3*i+2] - Rpos[3*j+2];
    float d  = sqrtf(dx*dx + dy*dy + dz*dz);
    float env = (d < RCUTF) ? 0.5f * (cosf(PI_F * d / RCUTF) + 1.0f) : 0.0f;
    rbf[lane] = sinf((float)(lane + 1) * PI_F * d / RCUTF) * env;
    __syncwarp();

    int f = lane & 15, h = lane >> 4;

    // Phase A: g[l][f] = sum_k rbf[k] * w_rad[l][k][f]
    {
        int ls = h ? 3 : 0, le = h ? 5 : 3;
        for (int l = ls; l < le; l++) {
            float acc = 0.f;
            #pragma unroll
            for (int k = 0; k < 32; k++)
                acc += rbf[k] * wrad_s[(l * 32 + k) * 16 + f];
            gsh[l * 16 + f] = acc;
        }
    }
    __syncwarp();

    // Phase B: per l, gw = W[t1,t2]+W[t2,t1]; cin = g*(ci+cj); cout = gw @ cin
    const float* clp[5] = {c0, c1, c2, c3, c4};
    int wb1 = (t1 * NT + t2) * 1280;
    int wb2 = (t2 * NT + t1) * 1280;
    #pragma unroll
    for (int l = 0; l < 5; l++) {
        const int nm = 2 * l + 1;
        const float* w1 = weight + wb1 + l * 256;
        const float* w2 = weight + wb2 + l * 256;
        #pragma unroll
        for (int idx = lane; idx < 256; idx += 32)
            gws[(idx >> 4) * 17 + (idx & 15)] = w1[idx] + w2[idx];
        const float* ci = clp[l] + (size_t)i * 16 * nm;
        const float* cj = clp[l] + (size_t)j * 16 * nm;
        for (int idx = lane; idx < 16 * nm; idx += 32) {
            int c = idx / nm, m = idx - c * nm;
            cin[m * 16 + c] = gsh[l * 16 + c] * (ci[idx] + cj[idx]);
        }
        __syncwarp();
        int mo = l * l;
        int mstart = h ? (nm + 1) / 2 : 0;
        int mend   = h ? nm : (nm + 1) / 2;
        for (int m = mstart; m < mend; m++) {
            float acc = 0.f;
            #pragma unroll
            for (int c = 0; c < 16; c++)
                acc += gws[f * 17 + c] * cin[m * 16 + c];
            coutS[(mo + m) * 17 + f] = acc;
        }
        __syncwarp();
    }

    // Phase C: E[xy][ag] = sum_f collp[xy][f] * cout[ag][f]  (only 121 needed)
    for (int t = lane; t < TBs.n_et; t += 32) {
        int xy = TBs.et_xy[t], ag = TBs.et_ag[t];
        float acc = 0.f;
        #pragma unroll
        for (int ff = 0; ff < 16; ff++)
            acc += collp_s[xy * 17 + ff] * coutS[ag * 17 + ff];
        Ew[xy * 25 + ag] = acc;
    }
    __syncwarp();

    // Phase D: 196 outputs, out[r][c] = sum_{l3,a'} cg[l1l2l3][m,n,a'] * E[xy][l3^2+a']
    float* op = out + (size_t)p * 196;
    for (int t = lane; t < 196; t += 32) {
        int xy = TBs.om_xy[t];
        int l1 = TBs.om_l1[t], l2 = TBs.om_l2[t];
        int mn = TBs.om_mn[t];
        float acc = 0.f;
        const float* Eb = Ew + xy * 25;
        for (int l3 = l1 - l2; l3 <= l1 + l2; l3++) {
            int nb = 2 * l3 + 1;
            const float* cgr = cg_s + TBs.cgoff[l1][l2][l3] + mn * nb;
            const float* Er = Eb + l3 * l3;
            for (int ap = 0; ap < nb; ap++)
                acc += cgr[ap] * Er[ap];
        }
        op[t] = acc;
    }
}

// ============================================================================
// Launch
// ============================================================================
extern "C" void kernel_launch(void* const* d_in, const int* in_sizes, int n_in,
                              void* d_out, int out_size) {
    const float* c0    = (const float*)d_in[0];
    const float* c1    = (const float*)d_in[1];
    const float* c2    = (const float*)d_in[2];
    const float* c3    = (const float*)d_in[3];
    const float* c4    = (const float*)d_in[4];
    const float* Rpos  = (const float*)d_in[5];
    const float* w_rad = (const float*)d_in[6];
    const float* wgt   = (const float*)d_in[7];
    const float* s_col = (const float*)d_in[8];
    const float* p_col = (const float*)d_in[9];
    const float* d_col = (const float*)d_in[10];
    const int*   Z     = (const int*)d_in[11];
    const int*   pairs = (const int*)d_in[12];
    const int*   aidx  = (const int*)d_in[13];
    float* out = (float*)d_out;

    int Pn = in_sizes[13];  // atom_idx has P elements

    CGParam cg;
    fill_cg(cg.v);

    size_t shmem = (size_t)WARPS * WSLOT * sizeof(float);
    cudaFuncSetAttribute(op_kernel, cudaFuncAttributeMaxDynamicSharedMemorySize, (int)shmem);

    int grid = (Pn + WARPS - 1) / WARPS;
    op_kernel<<<grid, 256, shmem>>>(c0, c1, c2, c3, c4, Rpos, w_rad, wgt,
                                    s_col, p_col, d_col, Z, pairs, aidx,
                                    out, Pn, cg);
}

// round 4
// speedup vs baseline: 1.0679x; 1.0679x over previous
#include <cuda_runtime.h>
#include <math.h>
#include <stdint.h>
#include <string.h>

#define PI_F 3.14159265358979323846f
#define RCUTF 5.0f
#define NT 10
#define WARPS 8

// ============================================================================
// Host-side exact replication of numpy RandomState(seed).standard_normal(...)
// ============================================================================
struct MT19937 {
    uint32_t mt[624];
    int mti;
    void seed(uint32_t s) {
        mt[0] = s;
        for (int i = 1; i < 624; i++)
            mt[i] = 1812433253u * (mt[i-1] ^ (mt[i-1] >> 30)) + (uint32_t)i;
        mti = 624;
    }
    uint32_t next() {
        if (mti >= 624) {
            for (int i = 0; i < 624; i++) {
                uint32_t y = (mt[i] & 0x80000000u) | (mt[(i+1) % 624] & 0x7fffffffu);
                mt[i] = mt[(i+397) % 624] ^ (y >> 1) ^ ((y & 1u) ? 2567483615u : 0u);
            }
            mti = 0;
        }
        uint32_t y = mt[mti++];
        y ^= y >> 11;
        y ^= (y << 7)  & 2636928640u;
        y ^= (y << 15) & 4022730752u;
        y ^= y >> 18;
        return y;
    }
    double rdouble() {
        uint32_t a = next() >> 5, b = next() >> 6;
        return (a * 67108864.0 + b) / 9007199254740992.0;
    }
};
struct GaussGen {
    MT19937 mt;
    bool has;
    double cached;
    void init(uint32_t s) { mt.seed(s); has = false; cached = 0.0; }
    double next() {
        if (has) { has = false; return cached; }
        double x1, x2, r2;
        do {
            x1 = 2.0 * mt.rdouble() - 1.0;
            x2 = 2.0 * mt.rdouble() - 1.0;
            r2 = x1 * x1 + x2 * x2;
        } while (r2 >= 1.0 || r2 == 0.0);
        double f = sqrt(-2.0 * log(r2) / r2);
        cached = f * x1; has = true;
        return f * x2;
    }
};

struct CGParam { float v[966]; };

static void fill_cg(float* out) {
    int off = 0;
    for (int l1 = 0; l1 < 3; l1++)
        for (int l2 = 0; l2 <= l1; l2++)
            for (int l3 = l1 - l2; l3 <= l1 + l2; l3++) {
                GaussGen g; g.init((uint32_t)(1000 + l1*100 + l2*10 + l3));
                int cnt = (2*l1+1) * (2*l2+1) * (2*l3+1);
                for (int q = 0; q < cnt; q++)
                    out[off++] = (float)g.next();
            }
}

// ============================================================================
// Compile-time index tables
// ============================================================================
struct Tables {
    unsigned char tri_x[21], tri_y[21];
    unsigned char et_xy[124], et_ag[124];
    short cgoff[3][3][5];
    unsigned char om_xy[196], om_l1[196], om_l2[196], om_mn[196];
    int n_et;
};

constexpr int trif(int x, int y) {
    int lo = x < y ? x : y, hi = x < y ? y : x;
    return hi * (hi + 1) / 2 + lo;
}

constexpr Tables makeTables() {
    Tables t{};
    for (int x = 0; x < 6; x++)
        for (int y = x; y < 6; y++) {
            t.tri_x[trif(x,y)] = (unsigned char)x;
            t.tri_y[trif(x,y)] = (unsigned char)y;
        }
    const int base[3] = {0, 3, 5};
    const int adim[3] = {3, 2, 1};
    {
        int off = 0;
        for (int l1 = 0; l1 < 3; l1++)
            for (int l2 = 0; l2 <= l1; l2++)
                for (int l3 = l1 - l2; l3 <= l1 + l2; l3++) {
                    t.cgoff[l1][l2][l3] = (short)off;
                    off += (2*l1+1) * (2*l2+1) * (2*l3+1);
                }
    }
    {
        bool seen[21][25] = {};
        int n = 0;
        for (int l1 = 0; l1 < 3; l1++)
            for (int l2 = 0; l2 <= l1; l2++)
                for (int xa = 0; xa < adim[l1]; xa++)
                    for (int xb = 0; xb < adim[l2]; xb++) {
                        int xy = trif(base[l1] + xa, base[l2] + xb);
                        for (int l3 = l1 - l2; l3 <= l1 + l2; l3++)
                            for (int ap = 0; ap < 2*l3 + 1; ap++) {
                                int ag = l3*l3 + ap;
                                if (!seen[xy][ag]) {
                                    seen[xy][ag] = true;
                                    t.et_xy[n] = (unsigned char)xy;
                                    t.et_ag[n] = (unsigned char)ag;
                                    n++;
                                }
                            }
                    }
        t.n_et = n; // 121
    }
    for (int r = 0; r < 14; r++)
        for (int c = 0; c < 14; c++) {
            int lr = r < 3 ? 0 : (r < 9 ? 1 : 2);
            int xr = r - (lr == 0 ? 0 : (lr == 1 ? 3 : 9));
            int lc = c < 3 ? 0 : (c < 9 ? 1 : 2);
            int xc = c - (lc == 0 ? 0 : (lc == 1 ? 3 : 9));
            int l1 = 0, l2 = 0, X = 0, Y = 0;
            if (lr >= lc) { l1 = lr; l2 = lc; X = xr; Y = xc; }
            else          { l1 = lc; l2 = lr; X = xc; Y = xr; }
            int N = 2*l2 + 1, A = adim[l1], B = adim[l2];
            int flat = X * (N * B) + Y;
            int b = flat % B; int tmp = flat / B;
            int a = tmp % A; tmp /= A;
            int n2 = tmp % N; int m = tmp / N;
            int idx = r * 14 + c;
            t.om_xy[idx] = (unsigned char)trif(base[l1] + a, base[l2] + b);
            t.om_l1[idx] = (unsigned char)l1;
            t.om_l2[idx] = (unsigned char)l2;
            t.om_mn[idx] = (unsigned char)(m * N + n2);
        }
    return t;
}

__constant__ Tables TBc = makeTables();

// ============================================================================
// Main kernel: one warp per pair, 8 pairs per 256-thread CTA
// Dynamic smem per warp (floats):
//   rbf   [0,32)
//   gsh   [32,112)      [l][16]
//   coutS [112,612)     [ag][20]  (stride 20, 16B aligned rows)
//   scr   [612,1200)    phase B: cin[9][16] (144) + gws[16*17] (272)
//                       phase C/D: E[21][25] (525)
// ============================================================================
#define WSLOT 1200

__global__ void __launch_bounds__(256) op_kernel(
    const float* __restrict__ c0, const float* __restrict__ c1,
    const float* __restrict__ c2, const float* __restrict__ c3,
    const float* __restrict__ c4,
    const float* __restrict__ Rpos, const float* __restrict__ w_rad,
    const float* __restrict__ weight,
    const float* __restrict__ s_col, const float* __restrict__ p_col,
    const float* __restrict__ d_col,
    const int* __restrict__ Z, const int* __restrict__ pairs,
    const int* __restrict__ aidx,
    float* __restrict__ out, int Pn,
    const __grid_constant__ CGParam cgp)
{
    __shared__ __align__(16) float wrad_s[2560];   // [l][k][f]
    __shared__ __align__(16) float cg_s[968];
    __shared__ __align__(16) float coll_s[96];     // 6 x 16
    __shared__ __align__(16) float collp_s[21 * 20]; // stride 20
    __shared__ Tables TBs;
    extern __shared__ __align__(16) float dyn[];

    int tid = threadIdx.x, w = tid >> 5, lane = tid & 31;

    for (int idx = tid; idx < 2560; idx += 256) wrad_s[idx] = w_rad[idx];
    for (int idx = tid; idx < 966;  idx += 256) cg_s[idx] = cgp.v[idx];
    if (tid < 96) {
        float v;
        if (tid < 48)      v = s_col[tid];
        else if (tid < 80) v = p_col[tid - 48];
        else               v = d_col[tid - 80];
        coll_s[tid] = v;
    }
    {
        const char* src = (const char*)&TBc;
        char* dst = (char*)&TBs;
        for (int idx = tid; idx < (int)sizeof(Tables); idx += 256) dst[idx] = src[idx];
    }
    __syncthreads();
    for (int idx = tid; idx < 336; idx += 256) {
        int t = idx >> 4, f = idx & 15;
        collp_s[t * 20 + f] = coll_s[TBs.tri_x[t] * 16 + f] * coll_s[TBs.tri_y[t] * 16 + f];
    }
    __syncthreads();

    int p = blockIdx.x * WARPS + w;
    if (p >= Pn) return;

    float* Wp    = dyn + w * WSLOT;
    float* rbf   = Wp;            // 32
    float* gsh   = Wp + 32;       // 80
    float* coutS = Wp + 112;      // 25*20 = 500
    float* scr   = Wp + 612;      // 588
    float* cin   = scr;           // [m][16]
    float* gws   = scr + 144;     // [c][17] -> [c*17 + b]
    float* Ew    = scr;           // [xy][25]

    int i = pairs[2 * p], j = pairs[2 * p + 1];
    int ai = aidx[p];
    int t1 = Z[pairs[2 * ai]], t2 = Z[pairs[2 * ai + 1]];

    float dx = Rpos[3*i+0] - Rpos[3*j+0];
    float dy = Rpos[3*i+1] - Rpos[3*j+1];
    float dz = Rpos[3*i+2] - Rpos[3*j+2];
    float d  = sqrtf(dx*dx + dy*dy + dz*dz);
    float env = (d < RCUTF) ? 0.5f * (cosf(PI_F * d / RCUTF) + 1.0f) : 0.0f;
    rbf[lane] = sinf((float)(lane + 1) * PI_F * d / RCUTF) * env;
    __syncwarp();

    int f = lane & 15, h = lane >> 4;

    // ---- Phase A: g[l][f] = sum_k rbf[k] * w_rad[l][k][f] ----
    {
        const float4* rv = (const float4*)rbf;
        #pragma unroll
        for (int li = 0; li < 3; li++) {
            if (!h || li < 2) {
                int l = h ? li + 3 : li;
                float acc = 0.f;
                #pragma unroll
                for (int q = 0; q < 8; q++) {
                    float4 r4 = rv[q];
                    const float* wr = wrad_s + (l * 32 + q * 4) * 16 + f;
                    acc = fmaf(r4.x, wr[0],  acc);
                    acc = fmaf(r4.y, wr[16], acc);
                    acc = fmaf(r4.z, wr[32], acc);
                    acc = fmaf(r4.w, wr[48], acc);
                }
                gsh[l * 16 + f] = acc;
            }
        }
    }
    __syncwarp();

    // ---- Phase B: per l, cout[b][m] = sum_c gw[b][c] * g[c]*(ci+cj)[c][m] ----
    const float* clp[5] = {c0, c1, c2, c3, c4};
    int wb1 = (t1 * NT + t2) * 1280;
    int wb2 = (t2 * NT + t1) * 1280;
    #pragma unroll
    for (int l = 0; l < 5; l++) {
        const int nm = 2 * l + 1;
        const int mh = (nm + 1) / 2;

        // stage gw transposed: gws[c*17+b] = w1[b*16+c] + w2[b*16+c]
        {
            const float4* w1v = (const float4*)(weight + wb1 + l * 256);
            const float4* w2v = (const float4*)(weight + wb2 + l * 256);
            #pragma unroll
            for (int q0 = 0; q0 < 2; q0++) {
                int qi = q0 * 32 + lane;       // 0..63
                float4 a  = w1v[qi];
                float4 b4 = w2v[qi];
                int idx = qi * 4;
                int b = idx >> 4, c = idx & 15;
                gws[(c+0)*17 + b] = a.x + b4.x;
                gws[(c+1)*17 + b] = a.y + b4.y;
                gws[(c+2)*17 + b] = a.z + b4.z;
                gws[(c+3)*17 + b] = a.w + b4.w;
            }
        }
        // stage cin[m][c] = g[l][c]*(ci+cj) (input layout [c][m])
        {
            const float* ci = clp[l] + (size_t)i * 16 * nm;
            const float* cj = clp[l] + (size_t)j * 16 * nm;
            #pragma unroll
            for (int idx = lane; idx < 16 * nm; idx += 32) {
                int c = idx / nm, m = idx - c * nm;
                cin[m * 16 + c] = gsh[l * 16 + c] * (ci[idx] + cj[idx]);
            }
        }
        __syncwarp();

        // each lane: 16 gw coefficients in registers
        float gwreg[16];
        #pragma unroll
        for (int c = 0; c < 16; c++) gwreg[c] = gws[c * 17 + f];

        #pragma unroll
        for (int mi = 0; mi < mh; mi++) {
            int m = mi + h * mh;
            if (m < nm) {
                const float4* cr = (const float4*)(cin + m * 16);
                float acc = 0.f;
                #pragma unroll
                for (int q = 0; q < 4; q++) {
                    float4 v = cr[q];
                    acc = fmaf(gwreg[4*q+0], v.x, acc);
                    acc = fmaf(gwreg[4*q+1], v.y, acc);
                    acc = fmaf(gwreg[4*q+2], v.z, acc);
                    acc = fmaf(gwreg[4*q+3], v.w, acc);
                }
                coutS[(l * l + m) * 20 + f] = acc;
            }
        }
        __syncwarp();
    }

    // ---- Phase C: E[xy][ag] = sum_f collp[xy][f] * cout[ag][f] ----
    for (int t = lane; t < TBs.n_et; t += 32) {
        int xy = TBs.et_xy[t], ag = TBs.et_ag[t];
        const float4* cr = (const float4*)(collp_s + xy * 20);
        const float4* qr = (const float4*)(coutS + ag * 20);
        float acc = 0.f;
        #pragma unroll
        for (int q = 0; q < 4; q++) {
            float4 a = cr[q], b4 = qr[q];
            acc = fmaf(a.x, b4.x, acc);
            acc = fmaf(a.y, b4.y, acc);
            acc = fmaf(a.z, b4.z, acc);
            acc = fmaf(a.w, b4.w, acc);
        }
        Ew[xy * 25 + ag] = acc;
    }
    __syncwarp();

    // ---- Phase D: 196 outputs ----
    float* op = out + (size_t)p * 196;
    for (int t = lane; t < 196; t += 32) {
        int xy = TBs.om_xy[t];
        int l1 = TBs.om_l1[t], l2 = TBs.om_l2[t];
        int mn = TBs.om_mn[t];
        float acc = 0.f;
        const float* Eb = Ew + xy * 25;
        for (int l3 = l1 - l2; l3 <= l1 + l2; l3++) {
            int nb = 2 * l3 + 1;
            const float* cgr = cg_s + TBs.cgoff[l1][l2][l3] + mn * nb;
            const float* Er = Eb + l3 * l3;
            for (int ap = 0; ap < nb; ap++)
                acc += cgr[ap] * Er[ap];
        }
        op[t] = acc;
    }
}

// ============================================================================
// Launch
// ============================================================================
extern "C" void kernel_launch(void* const* d_in, const int* in_sizes, int n_in,
                              void* d_out, int out_size) {
    const float* c0    = (const float*)d_in[0];
    const float* c1    = (const float*)d_in[1];
    const float* c2    = (const float*)d_in[2];
    const float* c3    = (const float*)d_in[3];
    const float* c4    = (const float*)d_in[4];
    const float* Rpos  = (const float*)d_in[5];
    const float* w_rad = (const float*)d_in[6];
    const float* wgt   = (const float*)d_in[7];
    const float* s_col = (const float*)d_in[8];
    const float* p_col = (const float*)d_in[9];
    const float* d_col = (const float*)d_in[10];
    const int*   Z     = (const int*)d_in[11];
    const int*   pairs = (const int*)d_in[12];
    const int*   aidx  = (const int*)d_in[13];
    float* out = (float*)d_out;

    int Pn = in_sizes[13];

    CGParam cg;
    fill_cg(cg.v);

    size_t shmem = (size_t)WARPS * WSLOT * sizeof(float);
    cudaFuncSetAttribute(op_kernel, cudaFuncAttributeMaxDynamicSharedMemorySize, (int)shmem);

    int grid = (Pn + WARPS - 1) / WARPS;
    op_kernel<<<grid, 256, shmem>>>(c0, c1, c2, c3, c4, Rpos, w_rad, wgt,
                                    s_col, p_col, d_col, Z, pairs, aidx,
                                    out, Pn, cg);
}